// round 5
// baseline (speedup 1.0000x reference)
#include <cuda_runtime.h>
#include <cuda_bf16.h>
#include <cstdint>
#include <cstddef>

#define BATCH  32768
#define DIM    512
#define NSTEPS 100
#define KC     64
#define AS_STRIDE 68     /* 128 x KC tile, padded    */
#define BS_STRIDE 136    /* KC x 128 tile, padded    */
#define SM_AS_FLOATS (128 * AS_STRIDE)
#define SM_BS_FLOATS (KC * BS_STRIDE)
#define SMEM_FLOATS (SM_AS_FLOATS + SM_BS_FLOATS + 128)
#define SMEM_BYTES  (SMEM_FLOATS * 4)

// ---------------------------------------------------------------------------
// Device scratch (no cudaMalloc allowed)
// ---------------------------------------------------------------------------
__device__ float g_f32a[(size_t)BATCH * DIM];
__device__ float g_f32b[(size_t)BATCH * DIM];
__device__ float g_tfa[(size_t)BATCH * DIM];   // tf32-rounded state (ping)
__device__ float g_tfb[(size_t)BATCH * DIM];   // tf32-rounded state (pong)
__device__ float g_wtf[(size_t)DIM * DIM];     // tf32-rounded W1 [k][n]
__device__ float g_s[DIM];                     // colsum of t-embed block

// ---------------------------------------------------------------------------
// tf32 helpers
// ---------------------------------------------------------------------------
__device__ __forceinline__ float to_tf32(float x) {
  uint32_t u;
  asm("cvt.rna.tf32.f32 %0, %1;" : "=r"(u) : "f"(x));
  return __uint_as_float(u);
}

// mma.sync m16n8k8 tf32: D = A*B + C (in place on c[])
__device__ __forceinline__ void mma_tf32(float c[4], const uint32_t a[4],
                                         const uint32_t b[2]) {
  asm volatile(
      "mma.sync.aligned.m16n8k8.row.col.f32.tf32.tf32.f32 "
      "{%0,%1,%2,%3}, {%4,%5,%6,%7}, {%8,%9}, {%0,%1,%2,%3};"
      : "+f"(c[0]), "+f"(c[1]), "+f"(c[2]), "+f"(c[3])
      : "r"(a[0]), "r"(a[1]), "r"(a[2]), "r"(a[3]), "r"(b[0]), "r"(b[1]));
}

// ---------------------------------------------------------------------------
// JAX threefry2x32 (exact) + partitionable random_bits + erfinv normal
// ---------------------------------------------------------------------------
__device__ __forceinline__ uint32_t random_bits_part(uint32_t k0, uint32_t k1,
                                                     uint32_t idx) {
  uint32_t k2 = k0 ^ k1 ^ 0x1BD11BDAu;
  uint32_t x0 = k0, x1 = idx + k1;   // counts: hi=0, lo=idx
#define TF_R(r) { x0 += x1; x1 = __funnelshift_l(x1, x1, (r)); x1 ^= x0; }
  TF_R(13) TF_R(15) TF_R(26) TF_R(6)
  x0 += k1; x1 += k2 + 1u;
  TF_R(17) TF_R(29) TF_R(16) TF_R(24)
  x0 += k2; x1 += k0 + 2u;
  TF_R(13) TF_R(15) TF_R(26) TF_R(6)
  x0 += k0; x1 += k1 + 3u;
  TF_R(17) TF_R(29) TF_R(16) TF_R(24)
  x0 += k1; x1 += k2 + 4u;
  TF_R(13) TF_R(15) TF_R(26) TF_R(6)
  x0 += k2; x1 += k0 + 5u;
#undef TF_R
  return x0 ^ x1;
}

__device__ __forceinline__ float bits_to_normal(uint32_t bits) {
  float f  = __uint_as_float((bits >> 9) | 0x3f800000u) - 1.0f;
  const float lo = -0.99999994f;                  // nextafter(-1, 0)
  float u  = fmaxf(lo, fmaf(f, 2.0f, lo));        // (1 - lo) rounds to 2.0f
  float w  = -log1pf(-u * u);
  bool  lt = w < 5.0f;
  float ww = lt ? (w - 2.5f) : (sqrtf(w) - 3.0f);
  float p;
  p = lt ? 2.81022636e-08f  : -0.000200214257f;
  p = fmaf(p, ww, lt ? 3.43273939e-07f : 0.000100950558f);
  p = fmaf(p, ww, lt ? -3.5233877e-06f : 0.00134934322f);
  p = fmaf(p, ww, lt ? -4.39150654e-06f : -0.00367342844f);
  p = fmaf(p, ww, lt ? 0.00021858087f  : 0.00573950773f);
  p = fmaf(p, ww, lt ? -0.00125372503f : -0.0076224613f);
  p = fmaf(p, ww, lt ? -0.00417768164f : 0.00943887047f);
  p = fmaf(p, ww, lt ? 0.246640727f    : 1.00167406f);
  p = fmaf(p, ww, lt ? 1.50140941f     : 2.83297682f);
  return 1.41421356f * (p * u);
}

// ---------------------------------------------------------------------------
// Prep kernels
// ---------------------------------------------------------------------------
__global__ void colsum_kernel(const float* __restrict__ W, float* __restrict__ s) {
  int j = threadIdx.x;
  float acc = 0.f;
  for (int d = 0; d < DIM; d++) acc += W[(size_t)(DIM + d) * DIM + j];
  s[j] = acc;
}

__global__ void prep_w_kernel(const float* __restrict__ W,
                              float* __restrict__ wtf) {
  size_t i = (size_t)blockIdx.x * blockDim.x + threadIdx.x;  // over DIM*DIM
  wtf[i] = to_tf32(W[i]);   // first DIM rows of W are the x-part, [k][n]
}

__global__ void prep_x_kernel(const float* __restrict__ x,
                              float* __restrict__ xtf) {
  size_t i = (size_t)blockIdx.x * blockDim.x + threadIdx.x;
  xtf[i] = to_tf32(x[i]);
}

// ---------------------------------------------------------------------------
// Fused step: tf32 mma.sync GEMM (128x128 tile) + threefry/erfinv epilogue
//   xn = x + 0.01*(x@W1 + t*s + b) + sqrt(0.02)*noise
// ---------------------------------------------------------------------------
__global__ __launch_bounds__(256, 2) void step_kernel(
    const float* __restrict__ xcur, const float* __restrict__ xtf,
    const float* __restrict__ wtf, const float* __restrict__ svec,
    const float* __restrict__ bvec, float* __restrict__ xout,
    float* __restrict__ tfout, float tval, uint32_t dk0, uint32_t dk1) {
  extern __shared__ float sm[];
  float* As = sm;                         // [128][AS_STRIDE]
  float* Bs = sm + SM_AS_FLOATS;          // [KC][BS_STRIDE]
  float* sdrift = Bs + SM_BS_FLOATS;      // [128] : t*s + b for this N tile

  const int tid  = threadIdx.x;
  const int lane = tid & 31;
  const int w    = tid >> 5;
  const int wm   = w >> 1;      // 0..3  (M warp)
  const int wn   = w & 1;       // 0..1  (N warp)
  const int Mt   = blockIdx.y;  // 0..255
  const int Nt   = blockIdx.x;  // 0..3

  if (tid < 128) {
    int gc = Nt * 128 + tid;
    sdrift[tid] = fmaf(tval, svec[gc], bvec[gc]);
  }

  float acc[2][8][4];
#pragma unroll
  for (int mt = 0; mt < 2; mt++)
#pragma unroll
    for (int nt = 0; nt < 8; nt++)
#pragma unroll
      for (int q = 0; q < 4; q++) acc[mt][nt][q] = 0.f;

  const int g_   = lane >> 2;   // groupID
  const int tg   = lane & 3;    // thread-in-group

  for (int chunk = 0; chunk < DIM / KC; chunk++) {
    const int k0 = chunk * KC;
    __syncthreads();
    // A tile: 128 rows x KC cols  (2048 float4, 8 per thread)
#pragma unroll
    for (int i = tid; i < 2048; i += 256) {
      int r  = i >> 4;
      int c4 = (i & 15) << 2;
      float4 v = *(const float4*)(xtf + (size_t)(Mt * 128 + r) * DIM + k0 + c4);
      *(float4*)(As + r * AS_STRIDE + c4) = v;
    }
    // B tile: KC rows(k) x 128 cols(n)
#pragma unroll
    for (int i = tid; i < 2048; i += 256) {
      int kr = i >> 5;
      int c4 = (i & 31) << 2;
      float4 v = *(const float4*)(wtf + (size_t)(k0 + kr) * DIM + Nt * 128 + c4);
      *(float4*)(Bs + kr * BS_STRIDE + c4) = v;
    }
    __syncthreads();
#pragma unroll
    for (int ks = 0; ks < KC / 8; ks++) {
      const int kb = ks * 8;
      uint32_t a[2][4];
#pragma unroll
      for (int mt = 0; mt < 2; mt++) {
        int r0 = wm * 32 + mt * 16 + g_;
        a[mt][0] = __float_as_uint(As[(r0)     * AS_STRIDE + kb + tg]);
        a[mt][1] = __float_as_uint(As[(r0 + 8) * AS_STRIDE + kb + tg]);
        a[mt][2] = __float_as_uint(As[(r0)     * AS_STRIDE + kb + tg + 4]);
        a[mt][3] = __float_as_uint(As[(r0 + 8) * AS_STRIDE + kb + tg + 4]);
      }
      uint32_t b[8][2];
#pragma unroll
      for (int nt = 0; nt < 8; nt++) {
        int bc = wn * 64 + nt * 8 + g_;
        b[nt][0] = __float_as_uint(Bs[(kb + tg)     * BS_STRIDE + bc]);
        b[nt][1] = __float_as_uint(Bs[(kb + tg + 4) * BS_STRIDE + bc]);
      }
#pragma unroll
      for (int mt = 0; mt < 2; mt++)
#pragma unroll
        for (int nt = 0; nt < 8; nt++)
          mma_tf32(acc[mt][nt], a[mt], b[nt]);
    }
  }

  // ---------------- epilogue: drift + threefry noise + state update --------
  const int r_base = Mt * 128 + wm * 32;
  const int c_base = Nt * 128 + wn * 64;
#pragma unroll
  for (int mt = 0; mt < 2; mt++) {
#pragma unroll
    for (int nt = 0; nt < 8; nt++) {
      int lcol = wn * 64 + nt * 8 + (tg << 1);      // local col (even)
      int col  = Nt * 128 + lcol;                    // global col
      float d0 = sdrift[lcol];
      float d1 = sdrift[lcol + 1];
#pragma unroll
      for (int h = 0; h < 2; h++) {                  // h=0: c0/c1, h=1: c2/c3
        int row = r_base + mt * 16 + g_ + h * 8;
        float S0 = acc[mt][nt][2 * h + 0] + d0;
        float S1 = acc[mt][nt][2 * h + 1] + d1;
        uint32_t idx = (uint32_t)(row * DIM + col);
        float n0 = bits_to_normal(random_bits_part(dk0, dk1, idx));
        float n1 = bits_to_normal(random_bits_part(dk0, dk1, idx + 1u));
        size_t gidx = (size_t)row * DIM + col;
        float2 xc = *(const float2*)(xcur + gidx);
        float xn0 = xc.x + 0.01f * S0 + 0.14142136f * n0;
        float xn1 = xc.y + 0.01f * S1 + 0.14142136f * n1;
        float2 o;  o.x = xn0;          o.y = xn1;
        float2 tf; tf.x = to_tf32(xn0); tf.y = to_tf32(xn1);
        *(float2*)(xout + gidx)  = o;
        *(float2*)(tfout + gidx) = tf;
      }
    }
  }
}

// ---------------------------------------------------------------------------
// Host-side threefry for fold_in(key(42), t)
// ---------------------------------------------------------------------------
static inline uint32_t h_rotl(uint32_t x, int r) { return (x << r) | (x >> (32 - r)); }
static void threefry_host(uint32_t k0, uint32_t k1, uint32_t x0, uint32_t x1,
                          uint32_t* o0, uint32_t* o1) {
  uint32_t k2 = k0 ^ k1 ^ 0x1BD11BDAu;
  x0 += k0; x1 += k1;
  static const int rots[2][4] = {{13, 15, 26, 6}, {17, 29, 16, 24}};
  uint32_t ks[3] = {k0, k1, k2};
  for (int g = 0; g < 5; g++) {
    const int* rr = rots[g & 1];
    for (int q = 0; q < 4; q++) { x0 += x1; x1 = h_rotl(x1, rr[q]); x1 ^= x0; }
    x0 += ks[(g + 1) % 3];
    x1 += ks[(g + 2) % 3] + (uint32_t)(g + 1);
  }
  *o0 = x0; *o1 = x1;
}

extern "C" void kernel_launch(void* const* d_in, const int* in_sizes, int n_in,
                              void* d_out, int out_size) {
  const float *x0 = nullptr, *W = nullptr, *bv = nullptr;
  for (int i = 0; i < n_in; i++) {
    if (in_sizes[i] == BATCH * DIM)        x0 = (const float*)d_in[i];
    else if (in_sizes[i] == 2 * DIM * DIM) W  = (const float*)d_in[i];
    else if (in_sizes[i] == DIM)           bv = (const float*)d_in[i];
  }

  void *pfa, *pfb, *pta, *ptb, *pw, *ps;
  cudaGetSymbolAddress(&pfa, g_f32a);
  cudaGetSymbolAddress(&pfb, g_f32b);
  cudaGetSymbolAddress(&pta, g_tfa);
  cudaGetSymbolAddress(&ptb, g_tfb);
  cudaGetSymbolAddress(&pw,  g_wtf);
  cudaGetSymbolAddress(&ps,  g_s);

  float* fbuf[2] = {(float*)pfa, (float*)pfb};
  float* tbuf[2] = {(float*)pta, (float*)ptb};

  cudaFuncSetAttribute(step_kernel, cudaFuncAttributeMaxDynamicSharedMemorySize,
                       SMEM_BYTES);

  colsum_kernel<<<1, DIM>>>(W, (float*)ps);
  prep_w_kernel<<<DIM * DIM / 256, 256>>>(W, (float*)pw);
  prep_x_kernel<<<BATCH * DIM / 256, 256>>>(x0, tbuf[0]);

  const float* cur = x0;
  dim3 grid(DIM / 128, BATCH / 128);   // (4, 256)
  for (int t = 0; t < NSTEPS; t++) {
    float* nxt = (t == NSTEPS - 1) ? (float*)d_out : fbuf[t & 1];
    uint32_t dk0, dk1;
    threefry_host(0u, 42u, 0u, (uint32_t)t, &dk0, &dk1);
    step_kernel<<<grid, 256, SMEM_BYTES>>>(
        cur, tbuf[t & 1], (const float*)pw, (const float*)ps, bv, nxt,
        tbuf[(t + 1) & 1], (float)t, dk0, dk1);
    cur = nxt;
  }
}

// round 6
// speedup vs baseline: 1.6055x; 1.6055x over previous
#include <cuda_runtime.h>
#include <cuda_bf16.h>
#include <cstdint>
#include <cstddef>

#define BATCH  32768
#define DIM    512
#define NSTEPS 100
#define KC     32
#define NCHUNK (DIM / KC)
#define AS_STRIDE 36      /* 128 x KC tile, stride in floats (pad 4)  */
#define BS_STRIDE 132     /* KC x 128 tile, stride in floats (pad 4)  */
#define AS_FLOATS (128 * AS_STRIDE)          /* 4608 */
#define BS_FLOATS (KC * BS_STRIDE)           /* 4224 */
#define STAGE_FLOATS (AS_FLOATS + BS_FLOATS) /* 8832 */
#define SMEM_FLOATS (2 * STAGE_FLOATS + 128)
#define SMEM_BYTES  (SMEM_FLOATS * 4)

// ---------------------------------------------------------------------------
// Device scratch (no cudaMalloc allowed)
// ---------------------------------------------------------------------------
__device__ float g_f32a[(size_t)BATCH * DIM];
__device__ float g_f32b[(size_t)BATCH * DIM];
__device__ float g_wtf[(size_t)DIM * DIM];     // tf32(RNA)-rounded W1 [k][n]
__device__ float g_s[DIM];                     // colsum of t-embed block

// ---------------------------------------------------------------------------
// helpers
// ---------------------------------------------------------------------------
__device__ __forceinline__ uint32_t smem_u32(const void* p) {
  uint32_t a;
  asm("{ .reg .u64 t; cvta.to.shared.u64 t, %1; cvt.u32.u64 %0, t; }"
      : "=r"(a) : "l"(p));
  return a;
}

__device__ __forceinline__ float to_tf32(float x) {
  uint32_t u;
  asm("cvt.rna.tf32.f32 %0, %1;" : "=r"(u) : "f"(x));
  return __uint_as_float(u);
}

__device__ __forceinline__ void cp_async16(uint32_t saddr, const void* gaddr) {
  asm volatile("cp.async.cg.shared.global [%0], [%1], 16;"
               :: "r"(saddr), "l"(gaddr));
}
#define CP_COMMIT() asm volatile("cp.async.commit_group;" ::: "memory")
template <int N>
__device__ __forceinline__ void cp_wait() {
  asm volatile("cp.async.wait_group %0;" :: "n"(N) : "memory");
}

// mma.sync m16n8k8 tf32: D = A*B + C (in place on c[])
__device__ __forceinline__ void mma_tf32(float c[4], const uint32_t a[4],
                                         const uint32_t b[2]) {
  asm volatile(
      "mma.sync.aligned.m16n8k8.row.col.f32.tf32.tf32.f32 "
      "{%0,%1,%2,%3}, {%4,%5,%6,%7}, {%8,%9}, {%0,%1,%2,%3};"
      : "+f"(c[0]), "+f"(c[1]), "+f"(c[2]), "+f"(c[3])
      : "r"(a[0]), "r"(a[1]), "r"(a[2]), "r"(a[3]), "r"(b[0]), "r"(b[1]));
}

// ---------------------------------------------------------------------------
// JAX threefry2x32 (exact) + partitionable random_bits + erfinv normal
// ---------------------------------------------------------------------------
__device__ __forceinline__ uint32_t random_bits_part(uint32_t k0, uint32_t k1,
                                                     uint32_t idx) {
  uint32_t k2 = k0 ^ k1 ^ 0x1BD11BDAu;
  uint32_t x0 = k0, x1 = idx + k1;   // counts: hi=0, lo=idx
#define TF_R(r) { x0 += x1; x1 = __funnelshift_l(x1, x1, (r)); x1 ^= x0; }
  TF_R(13) TF_R(15) TF_R(26) TF_R(6)
  x0 += k1; x1 += k2 + 1u;
  TF_R(17) TF_R(29) TF_R(16) TF_R(24)
  x0 += k2; x1 += k0 + 2u;
  TF_R(13) TF_R(15) TF_R(26) TF_R(6)
  x0 += k0; x1 += k1 + 3u;
  TF_R(17) TF_R(29) TF_R(16) TF_R(24)
  x0 += k1; x1 += k2 + 4u;
  TF_R(13) TF_R(15) TF_R(26) TF_R(6)
  x0 += k2; x1 += k0 + 5u;
#undef TF_R
  return x0 ^ x1;
}

__device__ __forceinline__ float bits_to_normal(uint32_t bits) {
  float f  = __uint_as_float((bits >> 9) | 0x3f800000u) - 1.0f;
  const float lo = -0.99999994f;                  // nextafter(-1, 0)
  float u  = fmaxf(lo, fmaf(f, 2.0f, lo));        // (1 - lo) rounds to 2.0f
  float w  = -log1pf(-u * u);
  bool  lt = w < 5.0f;
  float ww = lt ? (w - 2.5f) : (sqrtf(w) - 3.0f);
  float p;
  p = lt ? 2.81022636e-08f  : -0.000200214257f;
  p = fmaf(p, ww, lt ? 3.43273939e-07f : 0.000100950558f);
  p = fmaf(p, ww, lt ? -3.5233877e-06f : 0.00134934322f);
  p = fmaf(p, ww, lt ? -4.39150654e-06f : -0.00367342844f);
  p = fmaf(p, ww, lt ? 0.00021858087f  : 0.00573950773f);
  p = fmaf(p, ww, lt ? -0.00125372503f : -0.0076224613f);
  p = fmaf(p, ww, lt ? -0.00417768164f : 0.00943887047f);
  p = fmaf(p, ww, lt ? 0.246640727f    : 1.00167406f);
  p = fmaf(p, ww, lt ? 1.50140941f     : 2.83297682f);
  return 1.41421356f * (p * u);
}

// ---------------------------------------------------------------------------
// Prep kernels
// ---------------------------------------------------------------------------
__global__ void colsum_kernel(const float* __restrict__ W, float* __restrict__ s) {
  int j = threadIdx.x;
  float acc = 0.f;
  for (int d = 0; d < DIM; d++) acc += W[(size_t)(DIM + d) * DIM + j];
  s[j] = acc;
}

__global__ void prep_w_kernel(const float* __restrict__ W,
                              float* __restrict__ wtf) {
  size_t i = (size_t)blockIdx.x * blockDim.x + threadIdx.x;  // over DIM*DIM
  wtf[i] = to_tf32(W[i]);   // first DIM rows of W are the x-part, [k][n]
}

// ---------------------------------------------------------------------------
// Fused step: tf32 mma.sync GEMM (128x128 tile, cp.async 2-stage pipeline)
//   xn = x + 0.01*(x@W1 + t*s + b) + sqrt(0.02)*noise
// ---------------------------------------------------------------------------
__global__ __launch_bounds__(256, 2) void step_kernel(
    const float* __restrict__ xcur, const float* __restrict__ wtf,
    const float* __restrict__ svec, const float* __restrict__ bvec,
    float* __restrict__ xout, float tval, uint32_t dk0, uint32_t dk1) {
  extern __shared__ float sm[];
  float* sdrift = sm + 2 * STAGE_FLOATS;   // [128]
  const uint32_t sbase = smem_u32(sm);

  const int tid  = threadIdx.x;
  const int lane = tid & 31;
  const int w    = tid >> 5;
  const int wm   = w >> 1;      // 0..3  (M warp)
  const int wn   = w & 1;       // 0..1  (N warp)
  const int Mt   = blockIdx.y;  // 0..255
  const int Nt   = blockIdx.x;  // 0..3

  if (tid < 128) {
    int gc = Nt * 128 + tid;
    sdrift[tid] = fmaf(tval, svec[gc], bvec[gc]);
  }

  // per-thread cp.async source/dest precomputation
  const int a_r  = tid >> 1;                 // 0..127 (2 float4 per row pair)
  const int a_c4 = (tid & 1) << 4;           // 0 or 16 (floats); covers 32 w/ 2 issues? no:
  // A chunk = 128 rows x 32 floats = 1024 float4 -> 4 per thread.
  // Use i = tid + q*256: r = i>>3, c4 = (i&7)*4
  const int b_base_col = Nt * 128;

  auto issue_chunk = [&](int chunk, int s) {
    const int k0 = chunk * KC;
    const uint32_t abase = sbase + (uint32_t)(s * STAGE_FLOATS) * 4u;
    const uint32_t bbase = abase + (uint32_t)AS_FLOATS * 4u;
#pragma unroll
    for (int q = 0; q < 4; q++) {
      int i  = tid + q * 256;
      int r  = i >> 3;
      int c4 = (i & 7) << 2;
      cp_async16(abase + (uint32_t)(r * AS_STRIDE + c4) * 4u,
                 xcur + (size_t)(Mt * 128 + r) * DIM + k0 + c4);
    }
#pragma unroll
    for (int q = 0; q < 4; q++) {
      int i  = tid + q * 256;
      int kr = i >> 5;
      int c4 = (i & 31) << 2;
      cp_async16(bbase + (uint32_t)(kr * BS_STRIDE + c4) * 4u,
                 wtf + (size_t)(k0 + kr) * DIM + b_base_col + c4);
    }
    CP_COMMIT();
  };

  float acc[2][8][4];
#pragma unroll
  for (int mt = 0; mt < 2; mt++)
#pragma unroll
    for (int nt = 0; nt < 8; nt++)
#pragma unroll
      for (int q = 0; q < 4; q++) acc[mt][nt][q] = 0.f;

  const int g_ = lane >> 2;   // groupID
  const int tg = lane & 3;    // thread-in-group

  issue_chunk(0, 0);

  for (int chunk = 0; chunk < NCHUNK; chunk++) {
    if (chunk + 1 < NCHUNK) {
      issue_chunk(chunk + 1, (chunk + 1) & 1);
      cp_wait<1>();
    } else {
      cp_wait<0>();
    }
    __syncthreads();

    const float* As = sm + (chunk & 1) * STAGE_FLOATS;
    const float* Bs = As + AS_FLOATS;
#pragma unroll
    for (int ks = 0; ks < KC / 8; ks++) {
      const int kb = ks * 8;
      uint32_t a[2][4];
#pragma unroll
      for (int mt = 0; mt < 2; mt++) {
        int r0 = wm * 32 + mt * 16 + g_;
        a[mt][0] = __float_as_uint(As[(r0)     * AS_STRIDE + kb + tg]);
        a[mt][1] = __float_as_uint(As[(r0 + 8) * AS_STRIDE + kb + tg]);
        a[mt][2] = __float_as_uint(As[(r0)     * AS_STRIDE + kb + tg + 4]);
        a[mt][3] = __float_as_uint(As[(r0 + 8) * AS_STRIDE + kb + tg + 4]);
      }
      uint32_t b[8][2];
#pragma unroll
      for (int nt = 0; nt < 8; nt++) {
        int bc = wn * 64 + nt * 8 + g_;
        b[nt][0] = __float_as_uint(Bs[(kb + tg)     * BS_STRIDE + bc]);
        b[nt][1] = __float_as_uint(Bs[(kb + tg + 4) * BS_STRIDE + bc]);
      }
#pragma unroll
      for (int mt = 0; mt < 2; mt++)
#pragma unroll
        for (int nt = 0; nt < 8; nt++)
          mma_tf32(acc[mt][nt], a[mt], b[nt]);
    }
    __syncthreads();   // buffer (chunk&1) free for reuse at chunk+2
  }

  // ---------------- epilogue: drift + threefry noise + state update --------
  const int r_base = Mt * 128 + wm * 32;
#pragma unroll
  for (int mt = 0; mt < 2; mt++) {
#pragma unroll
    for (int nt = 0; nt < 8; nt++) {
      int lcol = wn * 64 + nt * 8 + (tg << 1);      // local col (even)
      int col  = Nt * 128 + lcol;                    // global col
      float d0 = sdrift[lcol];
      float d1 = sdrift[lcol + 1];
#pragma unroll
      for (int h = 0; h < 2; h++) {                  // h=0: c0/c1, h=1: c2/c3
        int row = r_base + mt * 16 + g_ + h * 8;
        float S0 = acc[mt][nt][2 * h + 0] + d0;
        float S1 = acc[mt][nt][2 * h + 1] + d1;
        uint32_t idx = (uint32_t)(row * DIM + col);
        float n0 = bits_to_normal(random_bits_part(dk0, dk1, idx));
        float n1 = bits_to_normal(random_bits_part(dk0, dk1, idx + 1u));
        size_t gidx = (size_t)row * DIM + col;
        float2 xc = *(const float2*)(xcur + gidx);
        float2 o;
        o.x = xc.x + 0.01f * S0 + 0.14142136f * n0;
        o.y = xc.y + 0.01f * S1 + 0.14142136f * n1;
        *(float2*)(xout + gidx) = o;
      }
    }
  }
}

// ---------------------------------------------------------------------------
// Host-side threefry for fold_in(key(42), t)
// ---------------------------------------------------------------------------
static inline uint32_t h_rotl(uint32_t x, int r) { return (x << r) | (x >> (32 - r)); }
static void threefry_host(uint32_t k0, uint32_t k1, uint32_t x0, uint32_t x1,
                          uint32_t* o0, uint32_t* o1) {
  uint32_t k2 = k0 ^ k1 ^ 0x1BD11BDAu;
  x0 += k0; x1 += k1;
  static const int rots[2][4] = {{13, 15, 26, 6}, {17, 29, 16, 24}};
  uint32_t ks[3] = {k0, k1, k2};
  for (int g = 0; g < 5; g++) {
    const int* rr = rots[g & 1];
    for (int q = 0; q < 4; q++) { x0 += x1; x1 = h_rotl(x1, rr[q]); x1 ^= x0; }
    x0 += ks[(g + 1) % 3];
    x1 += ks[(g + 2) % 3] + (uint32_t)(g + 1);
  }
  *o0 = x0; *o1 = x1;
}

extern "C" void kernel_launch(void* const* d_in, const int* in_sizes, int n_in,
                              void* d_out, int out_size) {
  const float *x0 = nullptr, *W = nullptr, *bv = nullptr;
  for (int i = 0; i < n_in; i++) {
    if (in_sizes[i] == BATCH * DIM)        x0 = (const float*)d_in[i];
    else if (in_sizes[i] == 2 * DIM * DIM) W  = (const float*)d_in[i];
    else if (in_sizes[i] == DIM)           bv = (const float*)d_in[i];
  }

  void *pfa, *pfb, *pw, *ps;
  cudaGetSymbolAddress(&pfa, g_f32a);
  cudaGetSymbolAddress(&pfb, g_f32b);
  cudaGetSymbolAddress(&pw,  g_wtf);
  cudaGetSymbolAddress(&ps,  g_s);

  float* fbuf[2] = {(float*)pfa, (float*)pfb};

  cudaFuncSetAttribute(step_kernel, cudaFuncAttributeMaxDynamicSharedMemorySize,
                       SMEM_BYTES);

  colsum_kernel<<<1, DIM>>>(W, (float*)ps);
  prep_w_kernel<<<DIM * DIM / 256, 256>>>(W, (float*)pw);

  const float* cur = x0;
  dim3 grid(DIM / 128, BATCH / 128);   // (4, 256)
  for (int t = 0; t < NSTEPS; t++) {
    float* nxt = (t == NSTEPS - 1) ? (float*)d_out : fbuf[t & 1];
    uint32_t dk0, dk1;
    threefry_host(0u, 42u, 0u, (uint32_t)t, &dk0, &dk1);
    step_kernel<<<grid, 256, SMEM_BYTES>>>(
        cur, (const float*)pw, (const float*)ps, bv, nxt, (float)t, dk0, dk1);
    cur = nxt;
  }
}

// round 9
// speedup vs baseline: 1.6063x; 1.0005x over previous
#include <cuda_runtime.h>
#include <cuda_bf16.h>
#include <cstdint>
#include <cstddef>

#define BATCH  32768
#define DIM    512
#define NSTEPS 100
#define KC     32
#define NCHUNK (DIM / KC)
#define AS_STRIDE 36      /* 128 x KC tile, stride in floats (pad 4)  */
#define BS_STRIDE 132     /* KC x 128 tile, stride in floats (pad 4)  */
#define AS_FLOATS (128 * AS_STRIDE)          /* 4608 */
#define BS_FLOATS (KC * BS_STRIDE)           /* 4224 */
#define STAGE_FLOATS (AS_FLOATS + BS_FLOATS) /* 8832 */
#define SMEM_FLOATS (2 * STAGE_FLOATS + 128)
#define SMEM_BYTES  (SMEM_FLOATS * 4)

// ---------------------------------------------------------------------------
// Device scratch (no cudaMalloc allowed)
// ---------------------------------------------------------------------------
__device__ float g_f32a[(size_t)BATCH * DIM];
__device__ float g_f32b[(size_t)BATCH * DIM];
__device__ float g_wtf[(size_t)DIM * DIM];     // tf32(RNA)-rounded W1 [k][n]
__device__ float g_s[DIM];                     // colsum of t-embed block

// ---------------------------------------------------------------------------
// helpers
// ---------------------------------------------------------------------------
__device__ __forceinline__ uint32_t smem_u32(const void* p) {
  uint32_t a;
  asm("{ .reg .u64 t; cvta.to.shared.u64 t, %1; cvt.u32.u64 %0, t; }"
      : "=r"(a) : "l"(p));
  return a;
}

__device__ __forceinline__ float to_tf32(float x) {
  uint32_t u;
  asm("cvt.rna.tf32.f32 %0, %1;" : "=r"(u) : "f"(x));
  return __uint_as_float(u);
}

__device__ __forceinline__ void cp_async16(uint32_t saddr, const void* gaddr) {
  asm volatile("cp.async.cg.shared.global [%0], [%1], 16;"
               :: "r"(saddr), "l"(gaddr));
}
#define CP_COMMIT() asm volatile("cp.async.commit_group;" ::: "memory")
template <int N>
__device__ __forceinline__ void cp_wait() {
  asm volatile("cp.async.wait_group %0;" :: "n"(N) : "memory");
}

// mma.sync m16n8k8 tf32: D = A*B + C (in place on c[])
__device__ __forceinline__ void mma_tf32(float c[4], const uint32_t a[4],
                                         const uint32_t b[2]) {
  asm volatile(
      "mma.sync.aligned.m16n8k8.row.col.f32.tf32.tf32.f32 "
      "{%0,%1,%2,%3}, {%4,%5,%6,%7}, {%8,%9}, {%0,%1,%2,%3};"
      : "+f"(c[0]), "+f"(c[1]), "+f"(c[2]), "+f"(c[3])
      : "r"(a[0]), "r"(a[1]), "r"(a[2]), "r"(a[3]), "r"(b[0]), "r"(b[1]));
}

// ---------------------------------------------------------------------------
// JAX threefry2x32 (exact) + partitionable random_bits + erfinv normal
// ---------------------------------------------------------------------------
__device__ __forceinline__ uint32_t random_bits_part(uint32_t k0, uint32_t k1,
                                                     uint32_t idx) {
  uint32_t k2 = k0 ^ k1 ^ 0x1BD11BDAu;
  uint32_t x0 = k0, x1 = idx + k1;   // counts: hi=0, lo=idx
#define TF_R(r) { x0 += x1; x1 = __funnelshift_l(x1, x1, (r)); x1 ^= x0; }
  TF_R(13) TF_R(15) TF_R(26) TF_R(6)
  x0 += k1; x1 += k2 + 1u;
  TF_R(17) TF_R(29) TF_R(16) TF_R(24)
  x0 += k2; x1 += k0 + 2u;
  TF_R(13) TF_R(15) TF_R(26) TF_R(6)
  x0 += k0; x1 += k1 + 3u;
  TF_R(17) TF_R(29) TF_R(16) TF_R(24)
  x0 += k1; x1 += k2 + 4u;
  TF_R(13) TF_R(15) TF_R(26) TF_R(6)
  x0 += k2; x1 += k0 + 5u;
#undef TF_R
  return x0 ^ x1;
}

__device__ __forceinline__ float bits_to_normal(uint32_t bits) {
  float f  = __uint_as_float((bits >> 9) | 0x3f800000u) - 1.0f;
  const float lo = -0.99999994f;                  // nextafter(-1, 0)
  float u  = fmaxf(lo, fmaf(f, 2.0f, lo));        // (1 - lo) rounds to 2.0f
  float w  = -log1pf(-u * u);
  bool  lt = w < 5.0f;
  float ww = lt ? (w - 2.5f) : (sqrtf(w) - 3.0f);
  float p;
  p = lt ? 2.81022636e-08f  : -0.000200214257f;
  p = fmaf(p, ww, lt ? 3.43273939e-07f : 0.000100950558f);
  p = fmaf(p, ww, lt ? -3.5233877e-06f : 0.00134934322f);
  p = fmaf(p, ww, lt ? -4.39150654e-06f : -0.00367342844f);
  p = fmaf(p, ww, lt ? 0.00021858087f  : 0.00573950773f);
  p = fmaf(p, ww, lt ? -0.00125372503f : -0.0076224613f);
  p = fmaf(p, ww, lt ? -0.00417768164f : 0.00943887047f);
  p = fmaf(p, ww, lt ? 0.246640727f    : 1.00167406f);
  p = fmaf(p, ww, lt ? 1.50140941f     : 2.83297682f);
  return 1.41421356f * (p * u);
}

// ---------------------------------------------------------------------------
// Prep kernels
// ---------------------------------------------------------------------------
__global__ void colsum_kernel(const float* __restrict__ W, float* __restrict__ s) {
  int j = threadIdx.x;
  float acc = 0.f;
  for (int d = 0; d < DIM; d++) acc += W[(size_t)(DIM + d) * DIM + j];
  s[j] = acc;
}

__global__ void prep_w_kernel(const float* __restrict__ W,
                              float* __restrict__ wtf) {
  size_t i = (size_t)blockIdx.x * blockDim.x + threadIdx.x;  // over DIM*DIM
  wtf[i] = to_tf32(W[i]);   // first DIM rows of W are the x-part, [k][n]
}

// ---------------------------------------------------------------------------
// Fused step: tf32 mma.sync GEMM (128x128 tile, cp.async 2-stage pipeline)
//   xn = x + 0.01*(x@W1 + t*s + b) + sqrt(0.02)*noise
// ---------------------------------------------------------------------------
__global__ __launch_bounds__(256, 2) void step_kernel(
    const float* __restrict__ xcur, const float* __restrict__ wtf,
    const float* __restrict__ svec, const float* __restrict__ bvec,
    float* __restrict__ xout, float tval, uint32_t dk0, uint32_t dk1) {
  extern __shared__ float sm[];
  float* sdrift = sm + 2 * STAGE_FLOATS;   // [128]
  const uint32_t sbase = smem_u32(sm);

  const int tid  = threadIdx.x;
  const int lane = tid & 31;
  const int w    = tid >> 5;
  const int wm   = w >> 1;      // 0..3  (M warp)
  const int wn   = w & 1;       // 0..1  (N warp)
  const int Mt   = blockIdx.y;  // 0..255
  const int Nt   = blockIdx.x;  // 0..3

  if (tid < 128) {
    int gc = Nt * 128 + tid;
    sdrift[tid] = fmaf(tval, svec[gc], bvec[gc]);
  }

  // per-thread cp.async source/dest precomputation
  const int a_r  = tid >> 1;                 // 0..127 (2 float4 per row pair)
  const int a_c4 = (tid & 1) << 4;           // 0 or 16 (floats); covers 32 w/ 2 issues? no:
  // A chunk = 128 rows x 32 floats = 1024 float4 -> 4 per thread.
  // Use i = tid + q*256: r = i>>3, c4 = (i&7)*4
  const int b_base_col = Nt * 128;

  auto issue_chunk = [&](int chunk, int s) {
    const int k0 = chunk * KC;
    const uint32_t abase = sbase + (uint32_t)(s * STAGE_FLOATS) * 4u;
    const uint32_t bbase = abase + (uint32_t)AS_FLOATS * 4u;
#pragma unroll
    for (int q = 0; q < 4; q++) {
      int i  = tid + q * 256;
      int r  = i >> 3;
      int c4 = (i & 7) << 2;
      cp_async16(abase + (uint32_t)(r * AS_STRIDE + c4) * 4u,
                 xcur + (size_t)(Mt * 128 + r) * DIM + k0 + c4);
    }
#pragma unroll
    for (int q = 0; q < 4; q++) {
      int i  = tid + q * 256;
      int kr = i >> 5;
      int c4 = (i & 31) << 2;
      cp_async16(bbase + (uint32_t)(kr * BS_STRIDE + c4) * 4u,
                 wtf + (size_t)(k0 + kr) * DIM + b_base_col + c4);
    }
    CP_COMMIT();
  };

  float acc[2][8][4];
#pragma unroll
  for (int mt = 0; mt < 2; mt++)
#pragma unroll
    for (int nt = 0; nt < 8; nt++)
#pragma unroll
      for (int q = 0; q < 4; q++) acc[mt][nt][q] = 0.f;

  const int g_ = lane >> 2;   // groupID
  const int tg = lane & 3;    // thread-in-group

  issue_chunk(0, 0);

  for (int chunk = 0; chunk < NCHUNK; chunk++) {
    if (chunk + 1 < NCHUNK) {
      issue_chunk(chunk + 1, (chunk + 1) & 1);
      cp_wait<1>();
    } else {
      cp_wait<0>();
    }
    __syncthreads();

    const float* As = sm + (chunk & 1) * STAGE_FLOATS;
    const float* Bs = As + AS_FLOATS;
#pragma unroll
    for (int ks = 0; ks < KC / 8; ks++) {
      const int kb = ks * 8;
      uint32_t a[2][4];
#pragma unroll
      for (int mt = 0; mt < 2; mt++) {
        int r0 = wm * 32 + mt * 16 + g_;
        a[mt][0] = __float_as_uint(As[(r0)     * AS_STRIDE + kb + tg]);
        a[mt][1] = __float_as_uint(As[(r0 + 8) * AS_STRIDE + kb + tg]);
        a[mt][2] = __float_as_uint(As[(r0)     * AS_STRIDE + kb + tg + 4]);
        a[mt][3] = __float_as_uint(As[(r0 + 8) * AS_STRIDE + kb + tg + 4]);
      }
      uint32_t b[8][2];
#pragma unroll
      for (int nt = 0; nt < 8; nt++) {
        int bc = wn * 64 + nt * 8 + g_;
        b[nt][0] = __float_as_uint(Bs[(kb + tg)     * BS_STRIDE + bc]);
        b[nt][1] = __float_as_uint(Bs[(kb + tg + 4) * BS_STRIDE + bc]);
      }
#pragma unroll
      for (int mt = 0; mt < 2; mt++)
#pragma unroll
        for (int nt = 0; nt < 8; nt++)
          mma_tf32(acc[mt][nt], a[mt], b[nt]);
    }
    __syncthreads();   // buffer (chunk&1) free for reuse at chunk+2
  }

  // ---------------- epilogue: drift + threefry noise + state update --------
  const int r_base = Mt * 128 + wm * 32;
#pragma unroll
  for (int mt = 0; mt < 2; mt++) {
#pragma unroll
    for (int nt = 0; nt < 8; nt++) {
      int lcol = wn * 64 + nt * 8 + (tg << 1);      // local col (even)
      int col  = Nt * 128 + lcol;                    // global col
      float d0 = sdrift[lcol];
      float d1 = sdrift[lcol + 1];
#pragma unroll
      for (int h = 0; h < 2; h++) {                  // h=0: c0/c1, h=1: c2/c3
        int row = r_base + mt * 16 + g_ + h * 8;
        float S0 = acc[mt][nt][2 * h + 0] + d0;
        float S1 = acc[mt][nt][2 * h + 1] + d1;
        uint32_t idx = (uint32_t)(row * DIM + col);
        float n0 = bits_to_normal(random_bits_part(dk0, dk1, idx));
        float n1 = bits_to_normal(random_bits_part(dk0, dk1, idx + 1u));
        size_t gidx = (size_t)row * DIM + col;
        float2 xc = *(const float2*)(xcur + gidx);
        float2 o;
        o.x = xc.x + 0.01f * S0 + 0.14142136f * n0;
        o.y = xc.y + 0.01f * S1 + 0.14142136f * n1;
        *(float2*)(xout + gidx) = o;
      }
    }
  }
}

// ---------------------------------------------------------------------------
// Host-side threefry for fold_in(key(42), t)
// ---------------------------------------------------------------------------
static inline uint32_t h_rotl(uint32_t x, int r) { return (x << r) | (x >> (32 - r)); }
static void threefry_host(uint32_t k0, uint32_t k1, uint32_t x0, uint32_t x1,
                          uint32_t* o0, uint32_t* o1) {
  uint32_t k2 = k0 ^ k1 ^ 0x1BD11BDAu;
  x0 += k0; x1 += k1;
  static const int rots[2][4] = {{13, 15, 26, 6}, {17, 29, 16, 24}};
  uint32_t ks[3] = {k0, k1, k2};
  for (int g = 0; g < 5; g++) {
    const int* rr = rots[g & 1];
    for (int q = 0; q < 4; q++) { x0 += x1; x1 = h_rotl(x1, rr[q]); x1 ^= x0; }
    x0 += ks[(g + 1) % 3];
    x1 += ks[(g + 2) % 3] + (uint32_t)(g + 1);
  }
  *o0 = x0; *o1 = x1;
}

extern "C" void kernel_launch(void* const* d_in, const int* in_sizes, int n_in,
                              void* d_out, int out_size) {
  const float *x0 = nullptr, *W = nullptr, *bv = nullptr;
  for (int i = 0; i < n_in; i++) {
    if (in_sizes[i] == BATCH * DIM)        x0 = (const float*)d_in[i];
    else if (in_sizes[i] == 2 * DIM * DIM) W  = (const float*)d_in[i];
    else if (in_sizes[i] == DIM)           bv = (const float*)d_in[i];
  }

  void *pfa, *pfb, *pw, *ps;
  cudaGetSymbolAddress(&pfa, g_f32a);
  cudaGetSymbolAddress(&pfb, g_f32b);
  cudaGetSymbolAddress(&pw,  g_wtf);
  cudaGetSymbolAddress(&ps,  g_s);

  float* fbuf[2] = {(float*)pfa, (float*)pfb};

  cudaFuncSetAttribute(step_kernel, cudaFuncAttributeMaxDynamicSharedMemorySize,
                       SMEM_BYTES);

  colsum_kernel<<<1, DIM>>>(W, (float*)ps);
  prep_w_kernel<<<DIM * DIM / 256, 256>>>(W, (float*)pw);

  const float* cur = x0;
  dim3 grid(DIM / 128, BATCH / 128);   // (4, 256)
  for (int t = 0; t < NSTEPS; t++) {
    float* nxt = (t == NSTEPS - 1) ? (float*)d_out : fbuf[t & 1];
    uint32_t dk0, dk1;
    threefry_host(0u, 42u, 0u, (uint32_t)t, &dk0, &dk1);
    step_kernel<<<grid, 256, SMEM_BYTES>>>(
        cur, (const float*)pw, (const float*)ps, bv, nxt, (float)t, dk0, dk1);
    cur = nxt;
  }
}

// round 13
// speedup vs baseline: 2.0613x; 1.2833x over previous
#include <cuda_runtime.h>
#include <cuda_bf16.h>
#include <cstdint>
#include <cstddef>

#define BATCH  32768
#define DIM    512
#define NSTEPS 100
#define KC     32
#define NCHUNK (DIM / KC)
#define AS_STRIDE 36                          /* padded A row stride (floats) */
#define AS_FLOATS (128 * AS_STRIDE)           /* 4608 */
#define BS_FLOATS (KC * 128)                  /* 4096, fragment-packed */
#define STAGE_FLOATS (AS_FLOATS + BS_FLOATS)  /* 8704 */
#define SMEM_FLOATS (2 * STAGE_FLOATS + 128)
#define SMEM_BYTES  (SMEM_FLOATS * 4)

// ---------------------------------------------------------------------------
// Device scratch (no cudaMalloc allowed)
// ---------------------------------------------------------------------------
__device__ float g_f32a[(size_t)BATCH * DIM];
__device__ float g_f32b[(size_t)BATCH * DIM];
__device__ float g_nz0[(size_t)BATCH * DIM];   // noise ping
__device__ float g_nz1[(size_t)BATCH * DIM];   // noise pong
__device__ float g_wpk[(size_t)DIM * DIM];     // fragment-packed tf32 W1
__device__ float g_s[DIM];                     // colsum of t-embed block

// ---------------------------------------------------------------------------
// helpers
// ---------------------------------------------------------------------------
__device__ __forceinline__ uint32_t smem_u32(const void* p) {
  uint32_t a;
  asm("{ .reg .u64 t; cvta.to.shared.u64 t, %1; cvt.u32.u64 %0, t; }"
      : "=r"(a) : "l"(p));
  return a;
}

__device__ __forceinline__ float to_tf32(float x) {
  uint32_t u;
  asm("cvt.rna.tf32.f32 %0, %1;" : "=r"(u) : "f"(x));
  return __uint_as_float(u);
}

__device__ __forceinline__ void cp_async16(uint32_t saddr, const void* gaddr) {
  asm volatile("cp.async.cg.shared.global [%0], [%1], 16;"
               :: "r"(saddr), "l"(gaddr));
}
#define CP_COMMIT() asm volatile("cp.async.commit_group;" ::: "memory")
template <int N>
__device__ __forceinline__ void cp_wait() {
  asm volatile("cp.async.wait_group %0;" :: "n"(N) : "memory");
}

// mma.sync m16n8k8 tf32: D = A*B + C (in place on c[])
__device__ __forceinline__ void mma_tf32(float c[4], const uint32_t a[4],
                                         uint32_t b0, uint32_t b1) {
  asm volatile(
      "mma.sync.aligned.m16n8k8.row.col.f32.tf32.tf32.f32 "
      "{%0,%1,%2,%3}, {%4,%5,%6,%7}, {%8,%9}, {%0,%1,%2,%3};"
      : "+f"(c[0]), "+f"(c[1]), "+f"(c[2]), "+f"(c[3])
      : "r"(a[0]), "r"(a[1]), "r"(a[2]), "r"(a[3]), "r"(b0), "r"(b1));
}

// ---------------------------------------------------------------------------
// JAX threefry2x32 (exact) + partitionable random_bits + fast erfinv normal
// ---------------------------------------------------------------------------
__device__ __forceinline__ uint32_t random_bits_part(uint32_t k0, uint32_t k1,
                                                     uint32_t idx) {
  uint32_t k2 = k0 ^ k1 ^ 0x1BD11BDAu;
  uint32_t x0 = k0, x1 = idx + k1;   // counts: hi=0, lo=idx
#define TF_R(r) { x0 += x1; x1 = __funnelshift_l(x1, x1, (r)); x1 ^= x0; }
  TF_R(13) TF_R(15) TF_R(26) TF_R(6)
  x0 += k1; x1 += k2 + 1u;
  TF_R(17) TF_R(29) TF_R(16) TF_R(24)
  x0 += k2; x1 += k0 + 2u;
  TF_R(13) TF_R(15) TF_R(26) TF_R(6)
  x0 += k0; x1 += k1 + 3u;
  TF_R(17) TF_R(29) TF_R(16) TF_R(24)
  x0 += k1; x1 += k2 + 4u;
  TF_R(13) TF_R(15) TF_R(26) TF_R(6)
  x0 += k2; x1 += k0 + 5u;
#undef TF_R
  return x0 ^ x1;
}

__device__ __forceinline__ float bits_to_normal(uint32_t bits) {
  float f  = __uint_as_float((bits >> 9) | 0x3f800000u) - 1.0f;
  const float lo = -0.99999994f;                  // nextafter(-1, 0)
  float u  = fmaxf(lo, fmaf(f, 2.0f, lo));        // (1 - lo) rounds to 2.0f
  float w  = -__logf(fmaf(-u, u, 1.0f));          // = -log(1-u^2), fma-exact arg
  bool  lt = w < 5.0f;
  float ws;
  asm("sqrt.approx.f32 %0, %1;" : "=f"(ws) : "f"(w));
  float ww = lt ? (w - 2.5f) : (ws - 3.0f);
  float p;
  p = lt ? 2.81022636e-08f  : -0.000200214257f;
  p = fmaf(p, ww, lt ? 3.43273939e-07f : 0.000100950558f);
  p = fmaf(p, ww, lt ? -3.5233877e-06f : 0.00134934322f);
  p = fmaf(p, ww, lt ? -4.39150654e-06f : -0.00367342844f);
  p = fmaf(p, ww, lt ? 0.00021858087f  : 0.00573950773f);
  p = fmaf(p, ww, lt ? -0.00125372503f : -0.0076224613f);
  p = fmaf(p, ww, lt ? -0.00417768164f : 0.00943887047f);
  p = fmaf(p, ww, lt ? 0.246640727f    : 1.00167406f);
  p = fmaf(p, ww, lt ? 1.50140941f     : 2.83297682f);
  return 1.41421356f * (p * u);
}

// ---------------------------------------------------------------------------
// Prep kernels
// ---------------------------------------------------------------------------
__global__ void colsum_kernel(const float* __restrict__ W, float* __restrict__ s) {
  int j = threadIdx.x;
  float acc = 0.f;
  for (int d = 0; d < DIM; d++) acc += W[(size_t)(DIM + d) * DIM + j];
  s[j] = acc;
}

// Fragment-packed tf32 W1: tile (ks, pp) = (k-step 8 rows, 16-col pair-block),
// 128 floats per tile laid out [lane][q]:
//   k = ks*8 + (lane&3) + (q&1)*4,  n = pp*16 + (q>>1)*8 + (lane>>2)
__global__ void prep_w_pack_kernel(const float* __restrict__ W,
                                   float* __restrict__ wpk) {
  int i = blockIdx.x * blockDim.x + threadIdx.x;   // over DIM*DIM
  int tile = i >> 7;
  int r    = i & 127;
  int lane = r >> 2, q = r & 3;
  int ks = tile >> 5, pp = tile & 31;
  int k = ks * 8 + (lane & 3) + (q & 1) * 4;
  int n = pp * 16 + (q >> 1) * 8 + (lane >> 2);
  wpk[i] = to_tf32(W[(size_t)k * DIM + n]);
}

// Seed noise for step 0
__global__ void prenoise_kernel(float* __restrict__ nz, uint32_t k0, uint32_t k1) {
  uint32_t gid = blockIdx.x * blockDim.x + threadIdx.x;
  uint32_t idx = gid * 2u;
  float2 v;
  v.x = bits_to_normal(random_bits_part(k0, k1, idx));
  v.y = bits_to_normal(random_bits_part(k0, k1, idx + 1u));
  *(float2*)(nz + idx) = v;
}

// ---------------------------------------------------------------------------
// Fused step: tf32 mma.sync GEMM + next-step noise gen interleaved in mainloop
//   xn = x + 0.01*(x@W1 + t*s + b) + sqrt(0.02)*noise_t   (noise_t preloaded)
// ---------------------------------------------------------------------------
__global__ __launch_bounds__(256, 2) void step_kernel(
    const float* __restrict__ xcur, const float* __restrict__ wpk,
    const float* __restrict__ svec, const float* __restrict__ bvec,
    float* __restrict__ xout,
    const float* __restrict__ nzin, float* __restrict__ nzout,
    float tval, uint32_t nk0, uint32_t nk1) {
  extern __shared__ float sm[];
  float* sdrift = sm + 2 * STAGE_FLOATS;   // [128]
  const uint32_t sbase = smem_u32(sm);

  const int tid  = threadIdx.x;
  const int lane = tid & 31;
  const int w    = tid >> 5;
  const int wm   = w >> 1;      // 0..3  (M warp)
  const int wn   = w & 1;       // 0..1  (N warp)
  const int Mt   = blockIdx.y;  // 0..255
  const int Nt   = blockIdx.x;  // 0..3

  if (tid < 128) {
    int gc = Nt * 128 + tid;
    sdrift[tid] = fmaf(tval, svec[gc], bvec[gc]);
  }

  const int g_ = lane >> 2;   // groupID
  const int tg = lane & 3;    // thread-in-group

  auto issue_chunk = [&](int chunk, int s) {
    const int k0 = chunk * KC;
    const uint32_t abase = sbase + (uint32_t)(s * STAGE_FLOATS) * 4u;
    const uint32_t bbase = abase + (uint32_t)AS_FLOATS * 4u;
#pragma unroll
    for (int q = 0; q < 4; q++) {          // A: 128 x 32 floats
      int i  = tid + q * 256;
      int r  = i >> 3;
      int c4 = (i & 7) << 2;
      cp_async16(abase + (uint32_t)(r * AS_STRIDE + c4) * 4u,
                 xcur + (size_t)(Mt * 128 + r) * DIM + k0 + c4);
    }
#pragma unroll
    for (int q = 0; q < 4; q++) {          // B: 32 packed tiles of 128 floats
      int i     = tid + q * 256;
      int tileL = i >> 5;                  // 0..31: ksL*8 + ppL
      int l16   = i & 31;
      int ksL   = tileL >> 3;
      int ppL   = tileL & 7;
      cp_async16(bbase + (uint32_t)(tileL * 128 + l16 * 4) * 4u,
                 wpk + ((size_t)((chunk * 4 + ksL) * 32 + Nt * 8 + ppL) * 128 +
                        l16 * 4));
    }
    CP_COMMIT();
  };

  float acc[2][8][4];
#pragma unroll
  for (int mt = 0; mt < 2; mt++)
#pragma unroll
    for (int nt = 0; nt < 8; nt++)
#pragma unroll
      for (int q = 0; q < 4; q++) acc[mt][nt][q] = 0.f;

  issue_chunk(0, 0);

  const int r_base = Mt * 128 + wm * 32;
  const int c_base = Nt * 128 + wn * 64;

  for (int chunk = 0; chunk < NCHUNK; chunk++) {
    if (chunk + 1 < NCHUNK) {
      issue_chunk(chunk + 1, (chunk + 1) & 1);
      cp_wait<1>();
    } else {
      cp_wait<0>();
    }
    __syncthreads();

    const float* As = sm + (chunk & 1) * STAGE_FLOATS;
    const float* Bs = As + AS_FLOATS;
#pragma unroll
    for (int ks = 0; ks < KC / 8; ks++) {
      const int kb = ks * 8;
      uint32_t a[2][4];
#pragma unroll
      for (int mt = 0; mt < 2; mt++) {
        int r0 = wm * 32 + mt * 16 + g_;
        a[mt][0] = __float_as_uint(As[(r0)     * AS_STRIDE + kb + tg]);
        a[mt][1] = __float_as_uint(As[(r0 + 8) * AS_STRIDE + kb + tg]);
        a[mt][2] = __float_as_uint(As[(r0)     * AS_STRIDE + kb + tg + 4]);
        a[mt][3] = __float_as_uint(As[(r0 + 8) * AS_STRIDE + kb + tg + 4]);
      }
      float4 bq[4];
#pragma unroll
      for (int pi = 0; pi < 4; pi++)
        bq[pi] = *(const float4*)(Bs + (ks * 8 + wn * 4 + pi) * 128 + lane * 4);
#pragma unroll
      for (int mt = 0; mt < 2; mt++)
#pragma unroll
        for (int pi = 0; pi < 4; pi++) {
          mma_tf32(acc[mt][2 * pi],     a[mt],
                   __float_as_uint(bq[pi].x), __float_as_uint(bq[pi].y));
          mma_tf32(acc[mt][2 * pi + 1], a[mt],
                   __float_as_uint(bq[pi].z), __float_as_uint(bq[pi].w));
        }
    }

    // -- interleaved: next step's noise, 2 float2 pairs per chunk (32 total) --
    // Per-thread noise positions: qi in 0..31 -> mt=qi>>4 (0..1), nt=(qi>>1)&7,
    // h=qi&1, matching the epilogue's 2x8x2 float2 layout exactly.
#pragma unroll
    for (int p = 0; p < 2; p++) {
      int qi  = chunk * 2 + p;            // 0..31
      int mt  = qi >> 4;                  // 0..1
      int nt  = (qi >> 1) & 7;            // 0..7
      int h   = qi & 1;                   // 0..1
      int row = r_base + mt * 16 + g_ + h * 8;
      int col = c_base + nt * 8 + (tg << 1);
      uint32_t idx = (uint32_t)(row * DIM + col);
      float2 nv;
      nv.x = bits_to_normal(random_bits_part(nk0, nk1, idx));
      nv.y = bits_to_normal(random_bits_part(nk0, nk1, idx + 1u));
      *(float2*)(nzout + (size_t)row * DIM + col) = nv;
    }

    __syncthreads();   // buffer (chunk&1) free for reuse at chunk+2
  }

  // ------------- epilogue: drift + preloaded noise + state update ----------
#pragma unroll
  for (int mt = 0; mt < 2; mt++) {
#pragma unroll
    for (int nt = 0; nt < 8; nt++) {
      int lcol = wn * 64 + nt * 8 + (tg << 1);
      float d0 = sdrift[lcol];
      float d1 = sdrift[lcol + 1];
      int col  = Nt * 128 + lcol;
#pragma unroll
      for (int h = 0; h < 2; h++) {
        int row = r_base + mt * 16 + g_ + h * 8;
        size_t gidx = (size_t)row * DIM + col;
        float S0 = acc[mt][nt][2 * h + 0] + d0;
        float S1 = acc[mt][nt][2 * h + 1] + d1;
        float2 nv = *(const float2*)(nzin + gidx);
        float2 xc = *(const float2*)(xcur + gidx);
        float2 o;
        o.x = xc.x + 0.01f * S0 + 0.14142136f * nv.x;
        o.y = xc.y + 0.01f * S1 + 0.14142136f * nv.y;
        *(float2*)(xout + gidx) = o;
      }
    }
  }
}

// ---------------------------------------------------------------------------
// Host-side threefry for fold_in(key(42), t)
// ---------------------------------------------------------------------------
static inline uint32_t h_rotl(uint32_t x, int r) { return (x << r) | (x >> (32 - r)); }
static void threefry_host(uint32_t k0, uint32_t k1, uint32_t x0, uint32_t x1,
                          uint32_t* o0, uint32_t* o1) {
  uint32_t k2 = k0 ^ k1 ^ 0x1BD11BDAu;
  x0 += k0; x1 += k1;
  static const int rots[2][4] = {{13, 15, 26, 6}, {17, 29, 16, 24}};
  uint32_t ks[3] = {k0, k1, k2};
  for (int g = 0; g < 5; g++) {
    const int* rr = rots[g & 1];
    for (int q = 0; q < 4; q++) { x0 += x1; x1 = h_rotl(x1, rr[q]); x1 ^= x0; }
    x0 += ks[(g + 1) % 3];
    x1 += ks[(g + 2) % 3] + (uint32_t)(g + 1);
  }
  *o0 = x0; *o1 = x1;
}

extern "C" void kernel_launch(void* const* d_in, const int* in_sizes, int n_in,
                              void* d_out, int out_size) {
  const float *x0 = nullptr, *W = nullptr, *bv = nullptr;
  for (int i = 0; i < n_in; i++) {
    if (in_sizes[i] == BATCH * DIM)        x0 = (const float*)d_in[i];
    else if (in_sizes[i] == 2 * DIM * DIM) W  = (const float*)d_in[i];
    else if (in_sizes[i] == DIM)           bv = (const float*)d_in[i];
  }

  void *pfa, *pfb, *pn0, *pn1, *pw, *ps;
  cudaGetSymbolAddress(&pfa, g_f32a);
  cudaGetSymbolAddress(&pfb, g_f32b);
  cudaGetSymbolAddress(&pn0, g_nz0);
  cudaGetSymbolAddress(&pn1, g_nz1);
  cudaGetSymbolAddress(&pw,  g_wpk);
  cudaGetSymbolAddress(&ps,  g_s);

  float* fbuf[2] = {(float*)pfa, (float*)pfb};
  float* nbuf[2] = {(float*)pn0, (float*)pn1};

  cudaFuncSetAttribute(step_kernel, cudaFuncAttributeMaxDynamicSharedMemorySize,
                       SMEM_BYTES);

  colsum_kernel<<<1, DIM>>>(W, (float*)ps);
  prep_w_pack_kernel<<<DIM * DIM / 256, 256>>>(W, (float*)pw);

  // noise for step 0
  uint32_t nk0, nk1;
  threefry_host(0u, 42u, 0u, 0u, &nk0, &nk1);
  prenoise_kernel<<<BATCH * DIM / 512, 256>>>(nbuf[0], nk0, nk1);

  const float* cur = x0;
  dim3 grid(DIM / 128, BATCH / 128);   // (4, 256)
  for (int t = 0; t < NSTEPS; t++) {
    float* nxt = (t == NSTEPS - 1) ? (float*)d_out : fbuf[t & 1];
    // key for NEXT step's noise (generated inside this step's mainloop)
    uint32_t k0n, k1n;
    threefry_host(0u, 42u, 0u, (uint32_t)(t + 1), &k0n, &k1n);
    step_kernel<<<grid, 256, SMEM_BYTES>>>(
        cur, (const float*)pw, (const float*)ps, bv, nxt,
        nbuf[t & 1], nbuf[(t + 1) & 1], (float)t, k0n, k1n);
    cur = nxt;
  }
}